// round 1
// baseline (speedup 1.0000x reference)
#include <cuda_runtime.h>
#include <math.h>

#define B_   2
#define T_   2048
#define C_   896
#define H_   14
#define HKV_ 2
#define D_   64
#define M_   (B_*T_)          // 4096
#define REP_ (H_/HKV_)        // 7

// ---------------- static scratch (no allocations allowed) ----------------
__device__ float g_q[(size_t)B_*H_*T_*D_];     // [B,H,T,D]
__device__ float g_k[(size_t)B_*HKV_*T_*D_];   // [B,HKV,T,D]
__device__ float g_v[(size_t)B_*HKV_*T_*D_];   // [B,HKV,T,D]
__device__ float g_att[(size_t)B_*T_*C_];      // [B,T,H*D]

// =====================================================================
// Kernel 1: fused QKV projection.  out[m,n] = x[m,:] @ W[:,n] + b[n]
// N_total = 1152 (q:0..895, k:896..1023, v:1024..1151).  64-wide N tiles
// align exactly with 64-dim heads, so each block writes one head slice.
// =====================================================================
__global__ __launch_bounds__(256)
void qkv_kernel(const float* __restrict__ x,
                const float* __restrict__ wq, const float* __restrict__ bq,
                const float* __restrict__ wk, const float* __restrict__ bk,
                const float* __restrict__ wv, const float* __restrict__ bv)
{
    __shared__ float xs[64*32];
    __shared__ float ws[32*64];

    const int tid = threadIdx.x;
    const int tx = tid & 15, ty = tid >> 4;
    const int n0 = blockIdx.x * 64;
    const int m0 = blockIdx.y * 64;

    const float* W; const float* bias; int ldw, col0, head, nheads; float* outb;
    if (n0 < 896)        { W = wq; bias = bq; ldw = 896; col0 = n0;        outb = g_q; nheads = H_; }
    else if (n0 < 1024)  { W = wk; bias = bk; ldw = 128; col0 = n0 - 896;  outb = g_k; nheads = HKV_; }
    else                 { W = wv; bias = bv; ldw = 128; col0 = n0 - 1024; outb = g_v; nheads = HKV_; }
    head = col0 >> 6;

    float acc[4][4];
    #pragma unroll
    for (int i = 0; i < 4; i++)
        #pragma unroll
        for (int j = 0; j < 4; j++) acc[i][j] = 0.f;

    const int xr = tid >> 3;          // 0..31 (x tile row, +32 second pass)
    const int xc = (tid & 7) * 4;     // 0..28
    const int wr = tid >> 4;          // 0..15 (w tile row, +16 second pass)
    const int wc = (tid & 15) * 4;    // 0..60

    for (int c0 = 0; c0 < C_; c0 += 32) {
        #pragma unroll
        for (int r = 0; r < 2; r++) {
            float4 v4 = *(const float4*)(x + (size_t)(m0 + xr + r*32)*C_ + c0 + xc);
            *(float4*)(xs + (xr + r*32)*32 + xc) = v4;
        }
        #pragma unroll
        for (int r = 0; r < 2; r++) {
            float4 v4 = *(const float4*)(W + (size_t)(c0 + wr + r*16)*ldw + col0 + wc);
            *(float4*)(ws + (wr + r*16)*64 + wc) = v4;
        }
        __syncthreads();
        #pragma unroll
        for (int kk = 0; kk < 32; kk++) {
            float a[4];
            #pragma unroll
            for (int i = 0; i < 4; i++) a[i] = xs[(ty*4 + i)*32 + kk];
            float4 w4 = *(float4*)(ws + kk*64 + tx*4);
            float bb[4] = {w4.x, w4.y, w4.z, w4.w};
            #pragma unroll
            for (int i = 0; i < 4; i++)
                #pragma unroll
                for (int j = 0; j < 4; j++) acc[i][j] += a[i]*bb[j];
        }
        __syncthreads();
    }

    float4 b4 = *(const float4*)(bias + col0 + tx*4);
    float bb[4] = {b4.x, b4.y, b4.z, b4.w};
    #pragma unroll
    for (int i = 0; i < 4; i++) {
        int m = m0 + ty*4 + i;
        int b = m >> 11, t = m & (T_-1);
        float4 o;
        o.x = acc[i][0] + bb[0];
        o.y = acc[i][1] + bb[1];
        o.z = acc[i][2] + bb[2];
        o.w = acc[i][3] + bb[3];
        *(float4*)(outb + (((size_t)(b*nheads + head))*T_ + t)*D_ + tx*4) = o;
    }
}

// =====================================================================
// Kernel 2: RoPE in place.  Pairs (d, d+32).  cos/sin are [T, D] with the
// two halves identical (emb = concat(freqs, freqs)).
// =====================================================================
__global__ void rope_kernel(const float* __restrict__ cs,
                            const float* __restrict__ sn,
                            int which, int total)
{
    int idx = blockIdx.x * blockDim.x + threadIdx.x;
    if (idx >= total) return;
    float* buf = which ? g_k : g_q;
    int p  = idx & 31;
    int t  = (idx >> 5) & (T_-1);
    int bh = idx >> 16;                     // / (32*2048)
    float* base = buf + ((size_t)bh*T_ + t)*D_;
    float c0 = cs[t*D_ + p],      s0 = sn[t*D_ + p];
    float c1 = cs[t*D_ + p + 32], s1 = sn[t*D_ + p + 32];
    float lo = base[p], hi = base[p + 32];
    base[p]      = lo*c0 - hi*s0;
    base[p + 32] = hi*c1 + lo*s1;
}

// =====================================================================
// Kernel 3: causal flash attention, fp32, 64x64 tiles, GQA.
// Shared: Qs(16K) + KP(16K, K tile then reused for P) + Vs(16K) = 48KB.
// =====================================================================
__global__ __launch_bounds__(256)
void attn_kernel()
{
    __shared__ float Qs[64*64];
    __shared__ float KP[64*64];
    __shared__ float Vs[64*64];

    const int tid = threadIdx.x;
    const int tx = tid & 15, ty = tid >> 4;
    const int qi = blockIdx.x;      // query tile
    const int h  = blockIdx.y;
    const int b  = blockIdx.z;
    const int hkv = h / REP_;

    const float* Q = g_q + (((size_t)(b*H_ + h))*T_ + qi*64)*D_;
    const float* K = g_k + ((size_t)(b*HKV_ + hkv))*T_*D_;
    const float* V = g_v + ((size_t)(b*HKV_ + hkv))*T_*D_;

    // Q tile is contiguous 4096 floats: flat copy
    #pragma unroll
    for (int r = 0; r < 4; r++)
        ((float4*)Qs)[tid + r*256] = ((const float4*)Q)[tid + r*256];

    float m_i[4], l_i[4], acc[4][4];
    #pragma unroll
    for (int i = 0; i < 4; i++) {
        m_i[i] = -1e30f; l_i[i] = 0.f;
        #pragma unroll
        for (int j = 0; j < 4; j++) acc[i][j] = 0.f;
    }

    for (int kt = 0; kt <= qi; kt++) {
        // K tile -> KP transposed to [d][n];  V tile flat copy [n][d]
        {
            int n   = tid >> 2;          // 0..63
            int dof = (tid & 3) * 16;    // 0,16,32,48
            const float* Kr = K + (size_t)(kt*64 + n)*D_ + dof;
            #pragma unroll
            for (int g = 0; g < 4; g++) {
                float4 k4 = *(const float4*)(Kr + g*4);
                KP[(dof + g*4 + 0)*64 + n] = k4.x;
                KP[(dof + g*4 + 1)*64 + n] = k4.y;
                KP[(dof + g*4 + 2)*64 + n] = k4.z;
                KP[(dof + g*4 + 3)*64 + n] = k4.w;
            }
            const float4* Vg = (const float4*)(V + (size_t)kt*64*D_);
            #pragma unroll
            for (int r = 0; r < 4; r++)
                ((float4*)Vs)[tid + r*256] = Vg[tid + r*256];
        }
        __syncthreads();

        // S = Q @ K^T  (4x4 per thread)
        float s[4][4];
        #pragma unroll
        for (int i = 0; i < 4; i++)
            #pragma unroll
            for (int j = 0; j < 4; j++) s[i][j] = 0.f;

        #pragma unroll
        for (int d = 0; d < 64; d++) {
            float a[4];
            #pragma unroll
            for (int i = 0; i < 4; i++) a[i] = Qs[(ty*4 + i)*64 + d];
            float4 k4 = *(float4*)(KP + d*64 + tx*4);
            float kb[4] = {k4.x, k4.y, k4.z, k4.w};
            #pragma unroll
            for (int i = 0; i < 4; i++)
                #pragma unroll
                for (int j = 0; j < 4; j++) s[i][j] += a[i]*kb[j];
        }
        __syncthreads();   // all K reads done; KP becomes P buffer

        const bool diag = (kt == qi);
        #pragma unroll
        for (int i = 0; i < 4; i++) {
            int qrow = qi*64 + ty*4 + i;
            float mx = -1e30f;
            #pragma unroll
            for (int j = 0; j < 4; j++) {
                s[i][j] *= 0.125f;
                if (diag && (kt*64 + tx*4 + j > qrow)) s[i][j] = -1e30f;
                mx = fmaxf(mx, s[i][j]);
            }
            #pragma unroll
            for (int off = 1; off < 16; off <<= 1)
                mx = fmaxf(mx, __shfl_xor_sync(0xffffffffu, mx, off));
            float newm  = fmaxf(m_i[i], mx);
            float alpha = __expf(m_i[i] - newm);
            m_i[i] = newm;
            float rs = 0.f;
            #pragma unroll
            for (int j = 0; j < 4; j++) {
                s[i][j] = __expf(s[i][j] - newm);
                rs += s[i][j];
            }
            #pragma unroll
            for (int off = 1; off < 16; off <<= 1)
                rs += __shfl_xor_sync(0xffffffffu, rs, off);
            l_i[i] = l_i[i]*alpha + rs;
            #pragma unroll
            for (int j = 0; j < 4; j++) {
                acc[i][j] *= alpha;
                KP[(ty*4 + i)*64 + tx*4 + j] = s[i][j];   // P tile [m][n]
            }
        }
        __syncthreads();   // P visible to all

        // O += P @ V
        #pragma unroll
        for (int n = 0; n < 64; n++) {
            float a[4];
            #pragma unroll
            for (int i = 0; i < 4; i++) a[i] = KP[(ty*4 + i)*64 + n];
            float4 v4 = *(float4*)(Vs + n*64 + tx*4);
            float vb[4] = {v4.x, v4.y, v4.z, v4.w};
            #pragma unroll
            for (int i = 0; i < 4; i++)
                #pragma unroll
                for (int j = 0; j < 4; j++) acc[i][j] += a[i]*vb[j];
        }
        __syncthreads();   // P,V reads done before next tile load
    }

    // epilogue: normalize, write [B,T,H*D]
    #pragma unroll
    for (int i = 0; i < 4; i++) {
        float inv = 1.f / l_i[i];
        int t = qi*64 + ty*4 + i;
        float4 o;
        o.x = acc[i][0]*inv; o.y = acc[i][1]*inv;
        o.z = acc[i][2]*inv; o.w = acc[i][3]*inv;
        *(float4*)(g_att + ((size_t)b*T_ + t)*C_ + h*64 + tx*4) = o;
    }
}

// =====================================================================
// Kernel 4: output projection  out = g_att[4096,896] @ wo[896,896]
// =====================================================================
__global__ __launch_bounds__(256)
void wo_kernel(const float* __restrict__ wo, float* __restrict__ out)
{
    __shared__ float xs[64*32];
    __shared__ float ws[32*64];

    const int tid = threadIdx.x;
    const int tx = tid & 15, ty = tid >> 4;
    const int n0 = blockIdx.x * 64;
    const int m0 = blockIdx.y * 64;

    float acc[4][4];
    #pragma unroll
    for (int i = 0; i < 4; i++)
        #pragma unroll
        for (int j = 0; j < 4; j++) acc[i][j] = 0.f;

    const int xr = tid >> 3;
    const int xc = (tid & 7) * 4;
    const int wr = tid >> 4;
    const int wc = (tid & 15) * 4;

    for (int c0 = 0; c0 < C_; c0 += 32) {
        #pragma unroll
        for (int r = 0; r < 2; r++) {
            float4 v4 = *(const float4*)(g_att + (size_t)(m0 + xr + r*32)*C_ + c0 + xc);
            *(float4*)(xs + (xr + r*32)*32 + xc) = v4;
        }
        #pragma unroll
        for (int r = 0; r < 2; r++) {
            float4 v4 = *(const float4*)(wo + (size_t)(c0 + wr + r*16)*C_ + n0 + wc);
            *(float4*)(ws + (wr + r*16)*64 + wc) = v4;
        }
        __syncthreads();
        #pragma unroll
        for (int kk = 0; kk < 32; kk++) {
            float a[4];
            #pragma unroll
            for (int i = 0; i < 4; i++) a[i] = xs[(ty*4 + i)*32 + kk];
            float4 w4 = *(float4*)(ws + kk*64 + tx*4);
            float bb[4] = {w4.x, w4.y, w4.z, w4.w};
            #pragma unroll
            for (int i = 0; i < 4; i++)
                #pragma unroll
                for (int j = 0; j < 4; j++) acc[i][j] += a[i]*bb[j];
        }
        __syncthreads();
    }

    #pragma unroll
    for (int i = 0; i < 4; i++) {
        int m = m0 + ty*4 + i;
        float4 o;
        o.x = acc[i][0]; o.y = acc[i][1]; o.z = acc[i][2]; o.w = acc[i][3];
        *(float4*)(out + (size_t)m*C_ + n0 + tx*4) = o;
    }
}

// =====================================================================
extern "C" void kernel_launch(void* const* d_in, const int* in_sizes, int n_in,
                              void* d_out, int out_size)
{
    const float* x  = (const float*)d_in[0];
    const float* wq = (const float*)d_in[1];
    const float* bq = (const float*)d_in[2];
    const float* wk = (const float*)d_in[3];
    const float* bk = (const float*)d_in[4];
    const float* wv = (const float*)d_in[5];
    const float* bv = (const float*)d_in[6];
    const float* wo = (const float*)d_in[7];
    const float* cs = (const float*)d_in[8];
    const float* sn = (const float*)d_in[9];
    // d_in[10] = mask, unused (causal mask computed analytically)
    float* out = (float*)d_out;

    qkv_kernel<<<dim3(18, 64), 256>>>(x, wq, bq, wk, bk, wv, bv);

    const int total_q = B_*H_*T_*32;    // 1,835,008
    const int total_k = B_*HKV_*T_*32;  //   262,144
    rope_kernel<<<(total_q + 255)/256, 256>>>(cs, sn, 0, total_q);
    rope_kernel<<<(total_k + 255)/256, 256>>>(cs, sn, 1, total_k);

    attn_kernel<<<dim3(T_/64, H_, B_), 256>>>();

    wo_kernel<<<dim3(C_/64, M_/64), 256>>>(wo, out);
}

// round 2
// speedup vs baseline: 1.9015x; 1.9015x over previous
#include <cuda_runtime.h>
#include <math.h>

#define B_   2
#define T_   2048
#define C_   896
#define H_   14
#define HKV_ 2
#define D_   64
#define M_   (B_*T_)          // 4096
#define REP_ (H_/HKV_)        // 7

// ---------------- static scratch (no allocations allowed) ----------------
__device__ float g_q[(size_t)B_*H_*T_*D_];     // [B,H,T,D]
__device__ float g_k[(size_t)B_*HKV_*T_*D_];   // [B,HKV,T,D]
__device__ float g_v[(size_t)B_*HKV_*T_*D_];   // [B,HKV,T,D]
__device__ float g_att[(size_t)B_*T_*C_];      // [B,T,H*D]

// ---------------- tf32 helpers ----------------
__device__ __forceinline__ unsigned f2tf(float f) {
    unsigned u;
    asm("cvt.rna.tf32.f32 %0, %1;" : "=r"(u) : "f"(f));
    return u;
}

__device__ __forceinline__ void mma_tf32(float c[4],
                                         unsigned a0, unsigned a1, unsigned a2, unsigned a3,
                                         unsigned b0, unsigned b1)
{
    asm volatile("mma.sync.aligned.m16n8k8.row.col.f32.tf32.tf32.f32 "
                 "{%0,%1,%2,%3}, {%4,%5,%6,%7}, {%8,%9}, {%0,%1,%2,%3};"
                 : "+f"(c[0]), "+f"(c[1]), "+f"(c[2]), "+f"(c[3])
                 : "r"(a0), "r"(a1), "r"(a2), "r"(a3), "r"(b0), "r"(b1));
}

// =====================================================================
// GEMM kernel (tf32 mma): MODE 0 = fused QKV proj, MODE 1 = WO proj.
// Block tile 128x64, 8 warps (4m x 2n), warp tile 32x32, k-chunk 32.
// =====================================================================
template<int MODE>
__global__ __launch_bounds__(256)
void gemm_kernel(const float* __restrict__ Aa,
                 const float* __restrict__ wq, const float* __restrict__ bq,
                 const float* __restrict__ wk, const float* __restrict__ bk,
                 const float* __restrict__ wv, const float* __restrict__ bv,
                 float* __restrict__ outw)
{
    __shared__ unsigned As[128*36];   // [m][k] tf32, pad to 36
    __shared__ unsigned Bs[32*68];    // [k][n] tf32, pad to 68

    const int tid  = threadIdx.x;
    const int lane = tid & 31, warp = tid >> 5;
    const int wm = warp >> 1, wn = warp & 1;
    const int gr = lane >> 2, tg = lane & 3;
    const int n0 = blockIdx.x * 64;
    const int m0 = blockIdx.y * 128;

    const float* W; const float* bias = bq; int ldw, col0;
    if (MODE == 0) {
        if (n0 < 896)       { W = wq; bias = bq; ldw = 896; col0 = n0;        }
        else if (n0 < 1024) { W = wk; bias = bk; ldw = 128; col0 = n0 - 896;  }
        else                { W = wv; bias = bv; ldw = 128; col0 = n0 - 1024; }
    } else {
        W = wq; ldw = 896; col0 = n0;   // wq slot carries wo for MODE 1
    }

    const float* Ap = (MODE == 1) ? (const float*)g_att : Aa;

    float acc[2][4][4];
    #pragma unroll
    for (int mt = 0; mt < 2; mt++)
        #pragma unroll
        for (int nt = 0; nt < 4; nt++)
            #pragma unroll
            for (int j = 0; j < 4; j++) acc[mt][nt][j] = 0.f;

    const int ar = tid >> 3, ac = (tid & 7) * 4;    // A loads: 32 rows/pass x4
    const int br = tid >> 4, bc = (tid & 15) * 4;   // B loads: 16 rows/pass x2

    for (int k0 = 0; k0 < C_; k0 += 32) {
        #pragma unroll
        for (int r = 0; r < 4; r++) {
            float4 a4 = *(const float4*)(Ap + (size_t)(m0 + ar + r*32)*C_ + k0 + ac);
            unsigned* p = As + (ar + r*32)*36 + ac;
            p[0] = f2tf(a4.x); p[1] = f2tf(a4.y); p[2] = f2tf(a4.z); p[3] = f2tf(a4.w);
        }
        #pragma unroll
        for (int r = 0; r < 2; r++) {
            float4 b4 = *(const float4*)(W + (size_t)(k0 + br + r*16)*ldw + col0 + bc);
            unsigned* p = Bs + (br + r*16)*68 + bc;
            p[0] = f2tf(b4.x); p[1] = f2tf(b4.y); p[2] = f2tf(b4.z); p[3] = f2tf(b4.w);
        }
        __syncthreads();

        #pragma unroll
        for (int kk = 0; kk < 4; kk++) {
            const int k8 = kk * 8;
            unsigned a[2][4];
            #pragma unroll
            for (int mt = 0; mt < 2; mt++) {
                const int mr = wm*32 + mt*16 + gr;
                a[mt][0] = As[mr*36      + k8 + tg];
                a[mt][1] = As[(mr+8)*36  + k8 + tg];
                a[mt][2] = As[mr*36      + k8 + tg + 4];
                a[mt][3] = As[(mr+8)*36  + k8 + tg + 4];
            }
            #pragma unroll
            for (int nt = 0; nt < 4; nt++) {
                const int nn = wn*32 + nt*8 + gr;
                unsigned b0 = Bs[(k8 + tg    )*68 + nn];
                unsigned b1 = Bs[(k8 + tg + 4)*68 + nn];
                mma_tf32(acc[0][nt], a[0][0], a[0][1], a[0][2], a[0][3], b0, b1);
                mma_tf32(acc[1][nt], a[1][0], a[1][1], a[1][2], a[1][3], b0, b1);
            }
        }
        __syncthreads();
    }

    // epilogue
    if (MODE == 0) {
        float* outb; int nheads;
        if (n0 < 896)       { outb = g_q; nheads = H_;   }
        else if (n0 < 1024) { outb = g_k; nheads = HKV_; }
        else                { outb = g_v; nheads = HKV_; }
        const int head = col0 >> 6;
        #pragma unroll
        for (int mt = 0; mt < 2; mt++) {
            #pragma unroll
            for (int half = 0; half < 2; half++) {
                const int m = m0 + wm*32 + mt*16 + gr + half*8;
                const int bb = m >> 11, t = m & (T_-1);
                #pragma unroll
                for (int nt = 0; nt < 4; nt++) {
                    const int nl = wn*32 + nt*8 + tg*2;
                    float2 v;
                    v.x = acc[mt][nt][half*2 + 0] + bias[col0 + nl];
                    v.y = acc[mt][nt][half*2 + 1] + bias[col0 + nl + 1];
                    *(float2*)(outb + (((size_t)(bb*nheads + head))*T_ + t)*D_ + nl) = v;
                }
            }
        }
    } else {
        #pragma unroll
        for (int mt = 0; mt < 2; mt++) {
            #pragma unroll
            for (int half = 0; half < 2; half++) {
                const int m = m0 + wm*32 + mt*16 + gr + half*8;
                #pragma unroll
                for (int nt = 0; nt < 4; nt++) {
                    const int nl = wn*32 + nt*8 + tg*2;
                    float2 v;
                    v.x = acc[mt][nt][half*2 + 0];
                    v.y = acc[mt][nt][half*2 + 1];
                    *(float2*)(outw + (size_t)m*C_ + n0 + nl) = v;
                }
            }
        }
    }
}

// =====================================================================
// RoPE in place (fp32). Pairs (d, d+32).
// =====================================================================
__global__ void rope_kernel(const float* __restrict__ cs,
                            const float* __restrict__ sn,
                            int which, int total)
{
    int idx = blockIdx.x * blockDim.x + threadIdx.x;
    if (idx >= total) return;
    float* buf = which ? g_k : g_q;
    int p  = idx & 31;
    int t  = (idx >> 5) & (T_-1);
    int bh = idx >> 16;
    float* base = buf + ((size_t)bh*T_ + t)*D_;
    float c0 = cs[t*D_ + p],      s0 = sn[t*D_ + p];
    float c1 = cs[t*D_ + p + 32], s1 = sn[t*D_ + p + 32];
    float lo = base[p], hi = base[p + 32];
    base[p]      = lo*c0 - hi*s0;
    base[p + 32] = hi*c1 + lo*s1;
}

// =====================================================================
// Flash attention, tf32 mma, 64x64 tiles, 4 warps (128 thr), GQA.
// Q fragments register-resident; P staged through KP (K buffer reuse).
// =====================================================================
__global__ __launch_bounds__(128)
void attn_kernel()
{
    __shared__ unsigned KP[64*68];   // K tile [key][d]; reused for P [m][key]; Q staging
    __shared__ unsigned Vs[64*68];   // V tile [key][d]

    const int tid  = threadIdx.x;
    const int lane = tid & 31, warp = tid >> 5;
    const int gr = lane >> 2, tg = lane & 3;
    const int qi = blockIdx.x;
    const int h  = blockIdx.y;
    const int b  = blockIdx.z;
    const int hkv = h / REP_;

    const float* Q = g_q + (((size_t)(b*H_ + h))*T_ + qi*64)*D_;
    const float* K = g_k + ((size_t)(b*HKV_ + hkv))*T_*D_;
    const float* V = g_v + ((size_t)(b*HKV_ + hkv))*T_*D_;

    // stage Q into KP (tf32), then lift to register fragments
    #pragma unroll
    for (int r = 0; r < 8; r++) {
        int f = tid + r*128;
        float4 q4 = ((const float4*)Q)[f];
        int e = f*4, row = e >> 6, col = e & 63;
        unsigned* p = KP + row*68 + col;
        p[0] = f2tf(q4.x); p[1] = f2tf(q4.y); p[2] = f2tf(q4.z); p[3] = f2tf(q4.w);
    }
    __syncthreads();

    const int m0 = warp * 16;
    unsigned QA[8][4];
    #pragma unroll
    for (int kc = 0; kc < 8; kc++) {
        QA[kc][0] = KP[(m0 + gr    )*68 + kc*8 + tg];
        QA[kc][1] = KP[(m0 + gr + 8)*68 + kc*8 + tg];
        QA[kc][2] = KP[(m0 + gr    )*68 + kc*8 + tg + 4];
        QA[kc][3] = KP[(m0 + gr + 8)*68 + kc*8 + tg + 4];
    }
    __syncthreads();

    float o[8][4];
    #pragma unroll
    for (int nt = 0; nt < 8; nt++)
        #pragma unroll
        for (int j = 0; j < 4; j++) o[nt][j] = 0.f;
    float mrow[2] = {-1e30f, -1e30f};
    float lrow[2] = {0.f, 0.f};
    const int grow0 = qi*64 + m0 + gr;

    for (int kt = 0; kt <= qi; kt++) {
        // load K, V tiles (tf32)
        {
            const int row = tid >> 1;
            const int cb  = (tid & 1) * 32;
            const float4* Kg = (const float4*)(K + (size_t)(kt*64 + row)*D_ + cb);
            const float4* Vg = (const float4*)(V + (size_t)(kt*64 + row)*D_ + cb);
            unsigned* kp = KP + row*68 + cb;
            unsigned* vp = Vs + row*68 + cb;
            #pragma unroll
            for (int g = 0; g < 8; g++) {
                float4 k4 = Kg[g];
                kp[g*4+0] = f2tf(k4.x); kp[g*4+1] = f2tf(k4.y);
                kp[g*4+2] = f2tf(k4.z); kp[g*4+3] = f2tf(k4.w);
                float4 v4 = Vg[g];
                vp[g*4+0] = f2tf(v4.x); vp[g*4+1] = f2tf(v4.y);
                vp[g*4+2] = f2tf(v4.z); vp[g*4+3] = f2tf(v4.w);
            }
        }
        __syncthreads();

        // S = Q @ K^T
        float s[8][4];
        #pragma unroll
        for (int nt = 0; nt < 8; nt++)
            #pragma unroll
            for (int j = 0; j < 4; j++) s[nt][j] = 0.f;

        #pragma unroll
        for (int nt = 0; nt < 8; nt++) {
            #pragma unroll
            for (int kc = 0; kc < 8; kc++) {
                unsigned b0 = KP[(nt*8 + gr)*68 + kc*8 + tg];
                unsigned b1 = KP[(nt*8 + gr)*68 + kc*8 + tg + 4];
                mma_tf32(s[nt], QA[kc][0], QA[kc][1], QA[kc][2], QA[kc][3], b0, b1);
            }
        }
        __syncthreads();   // all K reads done; KP becomes P buffer

        // online softmax (rows gr and gr+8 within warp tile)
        #pragma unroll
        for (int half = 0; half < 2; half++) {
            const int growg = grow0 + half*8;
            float mx = -1e30f;
            #pragma unroll
            for (int nt = 0; nt < 8; nt++) {
                #pragma unroll
                for (int j = 0; j < 2; j++) {
                    float v = s[nt][half*2 + j] * 0.125f;
                    int gc = kt*64 + nt*8 + tg*2 + j;
                    if (gc > growg) v = -1e30f;
                    s[nt][half*2 + j] = v;
                    mx = fmaxf(mx, v);
                }
            }
            mx = fmaxf(mx, __shfl_xor_sync(0xffffffffu, mx, 1));
            mx = fmaxf(mx, __shfl_xor_sync(0xffffffffu, mx, 2));
            float newm  = fmaxf(mrow[half], mx);
            float alpha = __expf(mrow[half] - newm);
            mrow[half] = newm;
            float rs = 0.f;
            #pragma unroll
            for (int nt = 0; nt < 8; nt++) {
                #pragma unroll
                for (int j = 0; j < 2; j++) {
                    float p = __expf(s[nt][half*2 + j] - newm);
                    s[nt][half*2 + j] = p;
                    rs += p;
                }
            }
            rs += __shfl_xor_sync(0xffffffffu, rs, 1);
            rs += __shfl_xor_sync(0xffffffffu, rs, 2);
            lrow[half] = lrow[half]*alpha + rs;
            #pragma unroll
            for (int nt = 0; nt < 8; nt++) {
                o[nt][half*2 + 0] *= alpha;
                o[nt][half*2 + 1] *= alpha;
            }
        }

        // write P (tf32) into KP: Ps[m][key]
        #pragma unroll
        for (int half = 0; half < 2; half++) {
            const int ml = m0 + gr + half*8;
            #pragma unroll
            for (int nt = 0; nt < 8; nt++) {
                uint2 pp;
                pp.x = f2tf(s[nt][half*2 + 0]);
                pp.y = f2tf(s[nt][half*2 + 1]);
                *(uint2*)(KP + ml*68 + nt*8 + tg*2) = pp;
            }
        }
        __syncthreads();   // P visible

        // O += P @ V
        #pragma unroll
        for (int kc = 0; kc < 8; kc++) {
            unsigned pa0 = KP[(m0 + gr    )*68 + kc*8 + tg];
            unsigned pa1 = KP[(m0 + gr + 8)*68 + kc*8 + tg];
            unsigned pa2 = KP[(m0 + gr    )*68 + kc*8 + tg + 4];
            unsigned pa3 = KP[(m0 + gr + 8)*68 + kc*8 + tg + 4];
            #pragma unroll
            for (int nt = 0; nt < 8; nt++) {
                unsigned b0 = Vs[(kc*8 + tg    )*68 + nt*8 + gr];
                unsigned b1 = Vs[(kc*8 + tg + 4)*68 + nt*8 + gr];
                mma_tf32(o[nt], pa0, pa1, pa2, pa3, b0, b1);
            }
        }
        __syncthreads();   // reads done before next tile load
    }

    // epilogue: normalize, write [B,T,H*D]
    const float inv0 = 1.f / lrow[0];
    const float inv1 = 1.f / lrow[1];
    const int t0 = qi*64 + m0 + gr;
    #pragma unroll
    for (int nt = 0; nt < 8; nt++) {
        const int col = h*64 + nt*8 + tg*2;
        float2 v0, v1;
        v0.x = o[nt][0]*inv0; v0.y = o[nt][1]*inv0;
        v1.x = o[nt][2]*inv1; v1.y = o[nt][3]*inv1;
        *(float2*)(g_att + ((size_t)b*T_ + t0    )*C_ + col) = v0;
        *(float2*)(g_att + ((size_t)b*T_ + t0 + 8)*C_ + col) = v1;
    }
}

// =====================================================================
extern "C" void kernel_launch(void* const* d_in, const int* in_sizes, int n_in,
                              void* d_out, int out_size)
{
    const float* x  = (const float*)d_in[0];
    const float* wq = (const float*)d_in[1];
    const float* bq = (const float*)d_in[2];
    const float* wk = (const float*)d_in[3];
    const float* bk = (const float*)d_in[4];
    const float* wv = (const float*)d_in[5];
    const float* bv = (const float*)d_in[6];
    const float* wo = (const float*)d_in[7];
    const float* cs = (const float*)d_in[8];
    const float* sn = (const float*)d_in[9];
    float* out = (float*)d_out;

    gemm_kernel<0><<<dim3(18, 32), 256>>>(x, wq, bq, wk, bk, wv, bv, nullptr);

    const int total_q = B_*H_*T_*32;
    const int total_k = B_*HKV_*T_*32;
    rope_kernel<<<(total_q + 255)/256, 256>>>(cs, sn, 0, total_q);
    rope_kernel<<<(total_k + 255)/256, 256>>>(cs, sn, 1, total_k);

    attn_kernel<<<dim3(T_/64, H_, B_), 128>>>();

    gemm_kernel<1><<<dim3(14, 32), 256>>>(nullptr, wo, nullptr, nullptr, nullptr,
                                          nullptr, nullptr, out);
}

// round 3
// speedup vs baseline: 2.4929x; 1.3110x over previous
#include <cuda_runtime.h>
#include <math.h>

#define B_   2
#define T_   2048
#define C_   896
#define H_   14
#define HKV_ 2
#define D_   64
#define M_   (B_*T_)          // 4096
#define REP_ (H_/HKV_)        // 7

// ---------------- static scratch ----------------
__device__ float g_q[(size_t)B_*H_*T_*D_];     // [B,H,T,D]
__device__ float g_k[(size_t)B_*HKV_*T_*D_];   // [B,HKV,T,D]
__device__ float g_v[(size_t)B_*HKV_*T_*D_];   // [B,HKV,T,D]
__device__ float g_att[(size_t)B_*T_*C_];      // [B,T,H*D]

// ---------------- helpers ----------------
__device__ __forceinline__ unsigned f2tf(float f) {
    unsigned u;
    asm("cvt.rna.tf32.f32 %0, %1;" : "=r"(u) : "f"(f));
    return u;
}
__device__ __forceinline__ unsigned sptr(const void* p) {
    return (unsigned)__cvta_generic_to_shared(p);
}
__device__ __forceinline__ void ldsm4(unsigned& r0, unsigned& r1,
                                      unsigned& r2, unsigned& r3, unsigned a) {
    asm volatile("ldmatrix.sync.aligned.m8n8.x4.shared.b16 {%0,%1,%2,%3}, [%4];"
                 : "=r"(r0), "=r"(r1), "=r"(r2), "=r"(r3) : "r"(a));
}
__device__ __forceinline__ void mma_tf32(float c[4],
                                         unsigned a0, unsigned a1, unsigned a2, unsigned a3,
                                         unsigned b0, unsigned b1)
{
    asm volatile("mma.sync.aligned.m16n8k8.row.col.f32.tf32.tf32.f32 "
                 "{%0,%1,%2,%3}, {%4,%5,%6,%7}, {%8,%9}, {%0,%1,%2,%3};"
                 : "+f"(c[0]), "+f"(c[1]), "+f"(c[2]), "+f"(c[3])
                 : "r"(a0), "r"(a1), "r"(a2), "r"(a3), "r"(b0), "r"(b1));
}
// S-accumulator (cols 2tg,2tg+1) -> A-fragment (cols tg,tg+4) quad permutation
__device__ __forceinline__ void p_frag(const float s4[4], unsigned a[4], int lane) {
    const int src_lo = (lane & ~3) | ((lane & 3) >> 1);
    const int src_hi = src_lo + 2;
    float y0 = __shfl_sync(0xffffffffu, s4[0], src_lo);
    float y1 = __shfl_sync(0xffffffffu, s4[1], src_lo);
    float y2 = __shfl_sync(0xffffffffu, s4[2], src_lo);
    float y3 = __shfl_sync(0xffffffffu, s4[3], src_lo);
    float z0 = __shfl_sync(0xffffffffu, s4[0], src_hi);
    float z1 = __shfl_sync(0xffffffffu, s4[1], src_hi);
    float z2 = __shfl_sync(0xffffffffu, s4[2], src_hi);
    float z3 = __shfl_sync(0xffffffffu, s4[3], src_hi);
    const bool odd = lane & 1;
    a[0] = f2tf(odd ? y1 : y0);
    a[1] = f2tf(odd ? y3 : y2);
    a[2] = f2tf(odd ? z1 : z0);
    a[3] = f2tf(odd ? z3 : z2);
}

// =====================================================================
// GEMM kernel (tf32 mma + ldmatrix A): MODE 0 = QKV proj, MODE 1 = WO.
// Block 128x64, 8 warps (4m x 2n), warp tile 32x32, k-chunk 32.
// =====================================================================
template<int MODE>
__global__ __launch_bounds__(256)
void gemm_kernel(const float* __restrict__ Aa,
                 const float* __restrict__ wq, const float* __restrict__ bq,
                 const float* __restrict__ wk, const float* __restrict__ bk,
                 const float* __restrict__ wv, const float* __restrict__ bv,
                 float* __restrict__ outw)
{
    __shared__ unsigned As[128*36];   // [m][k], 9-granule rows (odd -> LDSM conflict-free)
    __shared__ unsigned Bs[32*68];    // [k][n], pad 68

    const int tid  = threadIdx.x;
    const int lane = tid & 31, warp = tid >> 5;
    const int wm = warp >> 1, wn = warp & 1;
    const int gr = lane >> 2, tg = lane & 3;
    const int n0 = blockIdx.x * 64;
    const int m0 = blockIdx.y * 128;

    const float* W; const float* bias = bq; int ldw, col0;
    if (MODE == 0) {
        if (n0 < 896)       { W = wq; bias = bq; ldw = 896; col0 = n0;        }
        else if (n0 < 1024) { W = wk; bias = bk; ldw = 128; col0 = n0 - 896;  }
        else                { W = wv; bias = bv; ldw = 128; col0 = n0 - 1024; }
    } else {
        W = wq; ldw = 896; col0 = n0;   // wq slot carries wo
    }
    const float* Ap = (MODE == 1) ? (const float*)g_att : Aa;

    float acc[2][4][4];
    #pragma unroll
    for (int mt = 0; mt < 2; mt++)
        #pragma unroll
        for (int nt = 0; nt < 4; nt++)
            #pragma unroll
            for (int j = 0; j < 4; j++) acc[mt][nt][j] = 0.f;

    const int ar = tid >> 3, ac = (tid & 7) * 4;
    const int br = tid >> 4, bc = (tid & 15) * 4;
    // ldmatrix address components (A)
    const int lrow = (lane & 7) + ((lane >> 3) & 1) * 8;
    const int lg   = (lane >> 4) * 4;

    for (int k0 = 0; k0 < C_; k0 += 32) {
        #pragma unroll
        for (int r = 0; r < 4; r++) {
            float4 a4 = *(const float4*)(Ap + (size_t)(m0 + ar + r*32)*C_ + k0 + ac);
            uint4 u = make_uint4(f2tf(a4.x), f2tf(a4.y), f2tf(a4.z), f2tf(a4.w));
            *(uint4*)(As + (ar + r*32)*36 + ac) = u;
        }
        #pragma unroll
        for (int r = 0; r < 2; r++) {
            float4 b4 = *(const float4*)(W + (size_t)(k0 + br + r*16)*ldw + col0 + bc);
            uint4 u = make_uint4(f2tf(b4.x), f2tf(b4.y), f2tf(b4.z), f2tf(b4.w));
            *(uint4*)(Bs + (br + r*16)*68 + bc) = u;
        }
        __syncthreads();

        #pragma unroll
        for (int kk = 0; kk < 4; kk++) {
            const int k8 = kk * 8;
            unsigned a[2][4];
            #pragma unroll
            for (int mt = 0; mt < 2; mt++) {
                unsigned ad = sptr(As + (wm*32 + mt*16 + lrow)*36 + k8 + lg);
                ldsm4(a[mt][0], a[mt][1], a[mt][2], a[mt][3], ad);
            }
            #pragma unroll
            for (int nt = 0; nt < 4; nt++) {
                const int nn = wn*32 + nt*8 + gr;
                unsigned b0 = Bs[(k8 + tg    )*68 + nn];
                unsigned b1 = Bs[(k8 + tg + 4)*68 + nn];
                mma_tf32(acc[0][nt], a[0][0], a[0][1], a[0][2], a[0][3], b0, b1);
                mma_tf32(acc[1][nt], a[1][0], a[1][1], a[1][2], a[1][3], b0, b1);
            }
        }
        __syncthreads();
    }

    if (MODE == 0) {
        float* outb; int nheads;
        if (n0 < 896)       { outb = g_q; nheads = H_;   }
        else if (n0 < 1024) { outb = g_k; nheads = HKV_; }
        else                { outb = g_v; nheads = HKV_; }
        const int head = col0 >> 6;
        #pragma unroll
        for (int mt = 0; mt < 2; mt++) {
            #pragma unroll
            for (int half = 0; half < 2; half++) {
                const int m = m0 + wm*32 + mt*16 + gr + half*8;
                const int bb = m >> 11, t = m & (T_-1);
                #pragma unroll
                for (int nt = 0; nt < 4; nt++) {
                    const int nl = wn*32 + nt*8 + tg*2;
                    float2 v;
                    v.x = acc[mt][nt][half*2 + 0] + bias[col0 + nl];
                    v.y = acc[mt][nt][half*2 + 1] + bias[col0 + nl + 1];
                    *(float2*)(outb + (((size_t)(bb*nheads + head))*T_ + t)*D_ + nl) = v;
                }
            }
        }
    } else {
        #pragma unroll
        for (int mt = 0; mt < 2; mt++) {
            #pragma unroll
            for (int half = 0; half < 2; half++) {
                const int m = m0 + wm*32 + mt*16 + gr + half*8;
                #pragma unroll
                for (int nt = 0; nt < 4; nt++) {
                    const int nl = wn*32 + nt*8 + tg*2;
                    float2 v;
                    v.x = acc[mt][nt][half*2 + 0];
                    v.y = acc[mt][nt][half*2 + 1];
                    *(float2*)(outw + (size_t)m*C_ + n0 + nl) = v;
                }
            }
        }
    }
}

// =====================================================================
// RoPE in place (fp32).
// =====================================================================
__global__ void rope_kernel(const float* __restrict__ cs,
                            const float* __restrict__ sn,
                            int which, int total)
{
    int idx = blockIdx.x * blockDim.x + threadIdx.x;
    if (idx >= total) return;
    float* buf = which ? g_k : g_q;
    int p  = idx & 31;
    int t  = (idx >> 5) & (T_-1);
    int bh = idx >> 16;
    float* base = buf + ((size_t)bh*T_ + t)*D_;
    float c0 = cs[t*D_ + p],      s0 = sn[t*D_ + p];
    float c1 = cs[t*D_ + p + 32], s1 = sn[t*D_ + p + 32];
    float lo = base[p], hi = base[p + 32];
    base[p]      = lo*c0 - hi*s0;
    base[p + 32] = hi*c1 + lo*s1;
}

// =====================================================================
// Flash attention: tf32 mma, ldmatrix fragments, shuffle P path,
// double-buffered K/V, paired q-tiles for causal load balance.
// Dynamic smem: Ks[2][64*68] + Vt[2][64*68] = 17408 words = 68 KB.
// =====================================================================
#define KS_OFF(buf)  ((buf)*4352)
#define VT_OFF(buf)  (8704 + (buf)*4352)

__global__ __launch_bounds__(128)
void attn_kernel()
{
    extern __shared__ unsigned sm[];

    const int tid  = threadIdx.x;
    const int lane = tid & 31, warp = tid >> 5;
    const int gr = lane >> 2, tg = lane & 3;
    const int h  = blockIdx.y;
    const int b  = blockIdx.z;
    const int hkv = h / REP_;

    const float* Kbase = g_k + ((size_t)(b*HKV_ + hkv))*T_*D_;
    const float* Vbase = g_v + ((size_t)(b*HKV_ + hkv))*T_*D_;

    const int srow = tid & 63;            // staging: one key/q row per thread
    const int sdh  = (tid >> 6) * 32;     // d-half
    const int lrow = (lane & 7) + ((lane >> 3) & 1) * 8;   // ldmatrix A row part
    const int lg4  = (lane >> 4) * 4;                      // ldmatrix A granule
    const int brow = lane & 7;                             // ldmatrix B row part
    const int bg4  = (lane >> 3) * 4;                      // ldmatrix B granule

    #pragma unroll 1
    for (int pass = 0; pass < 2; pass++) {
        const int qi = pass == 0 ? blockIdx.x : (T_/64 - 1 - blockIdx.x);
        const float* Q = g_q + (((size_t)(b*H_ + h))*T_ + qi*64)*D_;

        __syncthreads();   // prior pass done reading shared
        // ---- stage Q (scaled by 1/8) into Ks buf0 ----
        {
            const float4* p = (const float4*)(Q + (size_t)srow*D_ + sdh);
            unsigned* q = sm + KS_OFF(0) + srow*68 + sdh;
            #pragma unroll
            for (int g = 0; g < 8; g++) {
                float4 v = p[g];
                uint4 u = make_uint4(f2tf(v.x*0.125f), f2tf(v.y*0.125f),
                                     f2tf(v.z*0.125f), f2tf(v.w*0.125f));
                *(uint4*)(q + g*4) = u;
            }
        }
        __syncthreads();
        // ---- lift Q fragments ----
        unsigned QA[8][4];
        #pragma unroll
        for (int kc = 0; kc < 8; kc++) {
            unsigned ad = sptr(sm + KS_OFF(0) + (warp*16 + lrow)*68 + kc*8 + lg4);
            ldsm4(QA[kc][0], QA[kc][1], QA[kc][2], QA[kc][3], ad);
        }
        __syncthreads();   // done reading Q staging before K tile 0 overwrites

        float o[8][4];
        #pragma unroll
        for (int nt = 0; nt < 8; nt++)
            #pragma unroll
            for (int j = 0; j < 4; j++) o[nt][j] = 0.f;
        float mrow[2] = {-1e30f, -1e30f};
        float lrw[2]  = {0.f, 0.f};
        const int grow0 = qi*64 + warp*16 + gr;

        // ---- stage tile 0 into buf 0 ----
        {
            const float4* kp = (const float4*)(Kbase + (size_t)srow*D_ + sdh);
            const float4* vp = (const float4*)(Vbase + (size_t)srow*D_ + sdh);
            unsigned* kd = sm + KS_OFF(0) + srow*68 + sdh;
            unsigned* vt = sm + VT_OFF(0);
            #pragma unroll
            for (int g = 0; g < 8; g++) {
                float4 kv = kp[g];
                *(uint4*)(kd + g*4) = make_uint4(f2tf(kv.x), f2tf(kv.y), f2tf(kv.z), f2tf(kv.w));
                float4 vv = vp[g];
                const int d0 = sdh + g*4;
                vt[(d0+0)*68 + srow] = f2tf(vv.x);
                vt[(d0+1)*68 + srow] = f2tf(vv.y);
                vt[(d0+2)*68 + srow] = f2tf(vv.z);
                vt[(d0+3)*68 + srow] = f2tf(vv.w);
            }
        }

        for (int kt = 0; kt <= qi; kt++) {
            __syncthreads();   // staging of buf[kt&1] complete; prior compute done
            if (kt < qi) {     // prefetch next tile into other buffer
                const int nb = (kt + 1) & 1;
                const float4* kp = (const float4*)(Kbase + (size_t)((kt+1)*64 + srow)*D_ + sdh);
                const float4* vp = (const float4*)(Vbase + (size_t)((kt+1)*64 + srow)*D_ + sdh);
                unsigned* kd = sm + KS_OFF(nb) + srow*68 + sdh;
                unsigned* vt = sm + VT_OFF(nb);
                #pragma unroll
                for (int g = 0; g < 8; g++) {
                    float4 kv = kp[g];
                    *(uint4*)(kd + g*4) = make_uint4(f2tf(kv.x), f2tf(kv.y), f2tf(kv.z), f2tf(kv.w));
                    float4 vv = vp[g];
                    const int d0 = sdh + g*4;
                    vt[(d0+0)*68 + srow] = f2tf(vv.x);
                    vt[(d0+1)*68 + srow] = f2tf(vv.y);
                    vt[(d0+2)*68 + srow] = f2tf(vv.z);
                    vt[(d0+3)*68 + srow] = f2tf(vv.w);
                }
            }
            const unsigned* Ksb = sm + KS_OFF(kt & 1);
            const unsigned* Vtb = sm + VT_OFF(kt & 1);

            // ---- S = (Q/8) @ K^T ----
            float s[8][4];
            #pragma unroll
            for (int nt = 0; nt < 8; nt++)
                #pragma unroll
                for (int j = 0; j < 4; j++) s[nt][j] = 0.f;
            #pragma unroll
            for (int kcp = 0; kcp < 4; kcp++) {
                #pragma unroll
                for (int nt = 0; nt < 8; nt++) {
                    unsigned b0, b1, b2, b3;
                    unsigned ad = sptr(Ksb + (nt*8 + brow)*68 + kcp*16 + bg4);
                    ldsm4(b0, b1, b2, b3, ad);
                    mma_tf32(s[nt], QA[2*kcp  ][0], QA[2*kcp  ][1], QA[2*kcp  ][2], QA[2*kcp  ][3], b0, b1);
                    mma_tf32(s[nt], QA[2*kcp+1][0], QA[2*kcp+1][1], QA[2*kcp+1][2], QA[2*kcp+1][3], b2, b3);
                }
            }

            // ---- online softmax ----
            const bool diag = (kt == qi);
            #pragma unroll
            for (int half = 0; half < 2; half++) {
                const int growg = grow0 + half*8;
                float mx = -1e30f;
                #pragma unroll
                for (int nt = 0; nt < 8; nt++) {
                    #pragma unroll
                    for (int j = 0; j < 2; j++) {
                        float v = s[nt][half*2 + j];
                        if (diag && (kt*64 + nt*8 + tg*2 + j > growg)) v = -1e30f;
                        s[nt][half*2 + j] = v;
                        mx = fmaxf(mx, v);
                    }
                }
                mx = fmaxf(mx, __shfl_xor_sync(0xffffffffu, mx, 1));
                mx = fmaxf(mx, __shfl_xor_sync(0xffffffffu, mx, 2));
                float newm  = fmaxf(mrow[half], mx);
                float alpha = __expf(mrow[half] - newm);
                mrow[half] = newm;
                float rs = 0.f;
                #pragma unroll
                for (int nt = 0; nt < 8; nt++) {
                    #pragma unroll
                    for (int j = 0; j < 2; j++) {
                        float p = __expf(s[nt][half*2 + j] - newm);
                        s[nt][half*2 + j] = p;
                        rs += p;
                    }
                }
                rs += __shfl_xor_sync(0xffffffffu, rs, 1);
                rs += __shfl_xor_sync(0xffffffffu, rs, 2);
                lrw[half] = lrw[half]*alpha + rs;
                #pragma unroll
                for (int nt = 0; nt < 8; nt++) {
                    o[nt][half*2 + 0] *= alpha;
                    o[nt][half*2 + 1] *= alpha;
                }
            }

            // ---- O += P @ V  (P fragments via quad shuffles) ----
            #pragma unroll
            for (int kcp = 0; kcp < 4; kcp++) {
                unsigned A0[4], A1[4];
                p_frag(s[2*kcp    ], A0, lane);
                p_frag(s[2*kcp + 1], A1, lane);
                #pragma unroll
                for (int nt = 0; nt < 8; nt++) {
                    unsigned b0, b1, b2, b3;
                    unsigned ad = sptr(Vtb + (nt*8 + brow)*68 + kcp*16 + bg4);
                    ldsm4(b0, b1, b2, b3, ad);
                    mma_tf32(o[nt], A0[0], A0[1], A0[2], A0[3], b0, b1);
                    mma_tf32(o[nt], A1[0], A1[1], A1[2], A1[3], b2, b3);
                }
            }
        }

        // ---- epilogue ----
        const float inv0 = 1.f / lrw[0];
        const float inv1 = 1.f / lrw[1];
        const int t0 = qi*64 + warp*16 + gr;
        #pragma unroll
        for (int nt = 0; nt < 8; nt++) {
            const int col = h*64 + nt*8 + tg*2;
            float2 v0, v1;
            v0.x = o[nt][0]*inv0; v0.y = o[nt][1]*inv0;
            v1.x = o[nt][2]*inv1; v1.y = o[nt][3]*inv1;
            *(float2*)(g_att + ((size_t)b*T_ + t0    )*C_ + col) = v0;
            *(float2*)(g_att + ((size_t)b*T_ + t0 + 8)*C_ + col) = v1;
        }
    }
}

// =====================================================================
extern "C" void kernel_launch(void* const* d_in, const int* in_sizes, int n_in,
                              void* d_out, int out_size)
{
    const float* x  = (const float*)d_in[0];
    const float* wq = (const float*)d_in[1];
    const float* bq = (const float*)d_in[2];
    const float* wk = (const float*)d_in[3];
    const float* bk = (const float*)d_in[4];
    const float* wv = (const float*)d_in[5];
    const float* bv = (const float*)d_in[6];
    const float* wo = (const float*)d_in[7];
    const float* cs = (const float*)d_in[8];
    const float* sn = (const float*)d_in[9];
    float* out = (float*)d_out;

    const int ATTN_SMEM = 17408 * 4;   // 69632 B
    static int configured = 0;
    if (!configured) {
        cudaFuncSetAttribute(attn_kernel,
                             cudaFuncAttributeMaxDynamicSharedMemorySize, ATTN_SMEM);
        configured = 1;
    }

    gemm_kernel<0><<<dim3(18, 32), 256>>>(x, wq, bq, wk, bk, wv, bv, nullptr);

    const int total_q = B_*H_*T_*32;
    const int total_k = B_*HKV_*T_*32;
    rope_kernel<<<(total_q + 255)/256, 256>>>(cs, sn, 0, total_q);
    rope_kernel<<<(total_k + 255)/256, 256>>>(cs, sn, 1, total_k);

    attn_kernel<<<dim3(16, H_, B_), 128, ATTN_SMEM>>>();

    gemm_kernel<1><<<dim3(14, 32), 256>>>(nullptr, wo, nullptr, nullptr, nullptr,
                                          nullptr, nullptr, out);
}